// round 14
// baseline (speedup 1.0000x reference)
#include <cuda_runtime.h>
#include <math.h>

#define R_MAX_F 6.0f
#define PI_F 3.14159265358979323846f
#define MAX_N 50048
#define MAX_DEG 64

// Static scratch (alloc-free rule). g_count zero at module load; k_gather
// re-zeroes after reading, so every execution starts from zero.
__device__ int g_count[MAX_N];
__device__ float4 g_edata[MAX_N * MAX_DEG];   // 51 MB (x,y,z,0) per edge

// Kernel 1: minimal bucket (R5-proven form): ONE edge per thread, raw payload,
// no math before the scattered store. Max TLP; nothing else in this grid.
__global__ void __launch_bounds__(256) k_bucket(const float* __restrict__ dr,
                                                const int* __restrict__ idx,
                                                int E) {
    int e = blockIdx.x * 256 + threadIdx.x;
    if (e >= E) return;
    int i = idx[e];
    int j = idx[E + e];
    if (i == j) return;

    float x = dr[3 * e + 0];
    float y = dr[3 * e + 1];
    float z = dr[3 * e + 2];

    int slot = atomicAdd(&g_count[i], 1);
    if (slot < MAX_DEG)
        g_edata[(i << 6) + slot] = make_float4(x, y, z, 0.0f);
}

// Per-edge accumulate on RAW payload (x,y,z). Normalization here is nearly
// free: rinv = rsqrt(d2), r = d2*rinv, and 1/r == rinv (replaces the old
// __fdividef MUFU), so net cost vs the normalized-payload version is ~5 FMA.
__device__ __forceinline__ void edge_accum(float4 v, float* acc, float& nbh) {
    const float s3   = 1.7320508075688772f;
    const float s15  = 3.872983346207417f;
    const float s104 = 0.7905694150420949f;
    const float s64  = 0.6123724356957945f;
    const float s152 = 1.9364916731037085f;

    float x = v.x, y = v.y, z = v.z;
    float d2 = fmaxf(x * x + y * y + z * z, 1e-24f);
    float rinv = rsqrtf(d2);
    float r = d2 * rinv;

    float s1, c1;
    __sincosf(r * (PI_F / R_MAX_F), &s1, &c1);
    float cut = (r < R_MAX_F) ? 0.5f * (c1 + 1.0f) : 0.0f;
    nbh += cut;

    float ux = x * rinv, uy = y * rinv, uz = z * rinv;
    float ux2 = ux * ux, uy2 = uy * uy, uz2 = uz * uz;
    acc[1]  += uy;
    acc[2]  += uz;
    acc[3]  += ux;
    acc[4]  += s3 * ux * uy;
    acc[5]  += s3 * uy * uz;
    acc[6]  += 0.5f * (3.0f * uz2 - 1.0f);
    acc[7]  += s3 * ux * uz;
    acc[8]  += 0.5f * s3 * (ux2 - uy2);
    acc[9]  += s104 * uy * (3.0f * ux2 - uy2);
    acc[10] += s15 * ux * uy * uz;
    acc[11] += s64 * uy * (5.0f * uz2 - 1.0f);
    acc[12] += 0.5f * uz * (5.0f * uz2 - 3.0f);
    acc[13] += s64 * ux * (5.0f * uz2 - 1.0f);
    acc[14] += s152 * uz * (ux2 - uy2);
    acc[15] += s104 * ux * (ux2 - 3.0f * uy2);

    // 1/r == rinv (r = d2*rinv, rinv^2*d2 = 1), so no division needed
    float pref = cut * 0.5773502691896258f * rinv;
    float twoc = 2.0f * c1;
    float sk_prev = 0.0f;
    float sk = s1;
#pragma unroll
    for (int m = 0; m < 16; m++) {
        acc[16 + m] += pref * sk;
        float sk_next = twoc * sk - sk_prev;
        sk_prev = sk;
        sk = sk_next;
    }
}

// Kernel 2: blocks [0,GB): 4 threads per node, software-pipelined, quad shfl
// reduction, single 128B store per node. Blocks [GB,GB+NB): coalesced
// embedding copy (fills gather's idle mem pipes).
__global__ void __launch_bounds__(128) k_gather(const int* __restrict__ Z,
                                                const float4* __restrict__ emb4,
                                                float4* __restrict__ out4,
                                                int N, int GB) {
    int tid = threadIdx.x;
    int b = blockIdx.x;

    if (b >= GB) {
        // --- Embedding copy: 16 float4 per thread, stride-128 coalesced ---
        long base = (long)(b - GB) * 2048 + tid;
        long total = (long)N * 32;
#pragma unroll
        for (int k = 0; k < 16; k++) {
            long lin = base + (long)k * 128;
            if (lin < total) {
                int n = (int)(lin >> 5);
                int c = (int)(lin & 31);
                int z = Z[n];
                float4 v = make_float4(0.f, 0.f, 0.f, 0.f);
                if (z != 0) v = emb4[z * 32 + c];
                out4[(size_t)n * 40 + c] = v;
            }
        }
        return;
    }

    int lane = tid & 3;
    int n = b * 32 + (tid >> 2);
    if (n >= N) return;

    int cnt = g_count[n];
    if (lane == 0) g_count[n] = 0;
    if (cnt > MAX_DEG) cnt = MAX_DEG;

    float acc[32];
#pragma unroll
    for (int k = 0; k < 32; k++) acc[k] = 0.0f;
    float nbh = 0.0f;

    const float4* ed = &g_edata[n << 6];

    int k = lane;
    bool va = (k < cnt), vb = (k + 4 < cnt);
    float4 a, b2;
    if (va) a = __ldg(&ed[k]);
    if (vb) b2 = __ldg(&ed[k + 4]);
    while (va) {
        int k2 = k + 8;
        bool vc = (k2 < cnt), vd = (k2 + 4 < cnt);
        float4 c, d;
        if (vc) c = __ldg(&ed[k2]);
        if (vd) d = __ldg(&ed[k2 + 4]);
        edge_accum(a, acc, nbh);
        if (vb) edge_accum(b2, acc, nbh);
        a = c; b2 = d; va = vc; vb = vd; k = k2;
    }

#pragma unroll
    for (int off = 2; off >= 1; off >>= 1) {
        nbh += __shfl_down_sync(0xFFFFFFFFu, nbh, off, 4);
#pragma unroll
        for (int q = 1; q < 32; q++)
            acc[q] += __shfl_down_sync(0xFFFFFFFFu, acc[q], off, 4);
    }
    acc[0] = (float)cnt;

    if (lane == 0) {
        float mask = (Z[n] != 0) ? 1.0f : 0.0f;
        float ps = ((nbh > 0.0f) ? 1.0f / nbh : 1.0f) * mask;

        float4* o = out4 + (size_t)n * 40 + 32;
#pragma unroll
        for (int q = 0; q < 4; q++)
            o[q] = make_float4(acc[4 * q] * ps, acc[4 * q + 1] * ps,
                               acc[4 * q + 2] * ps, acc[4 * q + 3] * ps);
#pragma unroll
        for (int q = 4; q < 8; q++)
            o[q] = make_float4(acc[4 * q] * mask, acc[4 * q + 1] * mask,
                               acc[4 * q + 2] * mask, acc[4 * q + 3] * mask);
    }
}

extern "C" void kernel_launch(void* const* d_in, const int* in_sizes, int n_in,
                              void* d_out, int out_size) {
    const float* dr  = (const float*)d_in[0];   // [E,3]
    const int*   Z   = (const int*)d_in[1];     // [N]
    const int*   idx = (const int*)d_in[2];     // [2,E]
    const float* emb = (const float*)d_in[3];   // [119,128]
    float* out = (float*)d_out;                 // [N,160]

    int E = in_sizes[2] / 2;
    int N = in_sizes[1];

    int EB = (E + 255) / 256;
    k_bucket<<<EB, 256>>>(dr, idx, E);

    int GB = (N + 31) / 32;                              // gather node blocks
    int NB = (int)(((long)N * 32 + 2047) / 2048);        // emb copy blocks
    k_gather<<<GB + NB, 128>>>(Z, (const float4*)emb, (float4*)out, N, GB);
}